// round 3
// baseline (speedup 1.0000x reference)
#include <cuda_runtime.h>
#include <cstddef>

typedef unsigned long long ull;

// ---------------------------------------------------------------------------
// Scratch (static device memory — no allocations anywhere)
// ---------------------------------------------------------------------------
__device__ float g_x1[32u * 8192u * 32u];
__device__ float g_x2[32u * 2048u * 64u];
__device__ float g_x3[32u * 512u * 128u];
__device__ float g_x4[32u * 128u * 256u];        // flat (32, 32768)
__device__ float g_p0[8192u * 3u * 32u * 32u];
__device__ float g_p1[2048u * 3u * 32u * 64u];
__device__ float g_p2[512u  * 3u * 32u * 128u];
__device__ float g_p3[128u  * 3u * 32u * 256u];
__device__ float g_pf[64u * 32u * 512u];
__device__ float g_h[32u * 512u];

// ---------------------------------------------------------------------------
// f32x2 packed helpers
// ---------------------------------------------------------------------------
__device__ __forceinline__ ull pack2(float lo, float hi) {
    ull r; asm("mov.b64 %0, {%1, %2};" : "=l"(r) : "f"(lo), "f"(hi)); return r;
}
__device__ __forceinline__ void unpack2(ull v, float& lo, float& hi) {
    asm("mov.b64 {%0, %1}, %2;" : "=f"(lo), "=f"(hi) : "l"(v));
}
__device__ __forceinline__ void fma2(ull& d, ull a, ull b) {
    asm("fma.rn.f32x2 %0, %1, %2, %0;" : "+l"(d) : "l"(a), "l"(b));
}
__device__ __forceinline__ float elu_f(float a) {
    return (a > 0.f) ? a : (__expf(a) - 1.f);
}

// ---------------------------------------------------------------------------
// Fused spiral_conv (+bias, ELU, *dw) for ONE (vertex, parent) per instance.
// Block = 256 threads = VSUB instances of TPI = COUT/2 threads.
// Instance: LANES = COUT/8 lanes (tx) x 4 pair-groups (pg).
// Thread owns 8 couts (c = tx*8+ic) x 4 batch-pairs -> 32 f32x2 accumulators.
// W is staged PRE-DUPLICATED: Wdup[jj][2c..2c+1] = (w, w)  -> no packing in
// the inner loop: per j = 4x LDS.128 (w) + 4x LDS.64 (g, broadcast) + 32 fma2.
// ---------------------------------------------------------------------------
template<int CIN, int COUT, int KC, int VSUB>
__global__ void __launch_bounds__(256, 2) stage_conv(
    const float* __restrict__ xin,     // (32, Vin, CIN)
    const int*   __restrict__ spiral,  // (Vin, 12)
    const int*   __restrict__ didx,    // (Vout, 3)
    const float* __restrict__ dw,      // (Vout, 3)
    const float* __restrict__ W,       // (12*CIN, COUT)
    const float* __restrict__ bias,    // (COUT)
    float* __restrict__ part,          // (Vout*3, 32, COUT)
    int Vin, int Vout)
{
    constexpr int S     = 12;
    constexpr int FAN   = S * CIN;
    constexpr int TPI   = COUT / 2;
    constexpr int LANES = COUT / 8;
    constexpr int GSROW = 34;
    constexpr int GSZ   = KC * GSROW;          // floats per instance chunk
    constexpr int NG    = VSUB * KC * 32;      // gather elements per chunk

    extern __shared__ float sm[];
    float* Ws = sm;                            // [KC][2*COUT]  duplicated pairs
    float* gs = sm + KC * 2 * COUT;            // [VSUB][KC][GSROW]
    __shared__ int   s_sidx[VSUB][S];
    __shared__ float s_wk[VSUB];

    const int t    = threadIdx.x;
    const int inst = t / TPI;
    const int ti   = t % TPI;
    const int tx   = ti % LANES;
    const int pg   = ti / LANES;               // 0..3
    const int vk0  = blockIdx.x * VSUB;

    if (t < VSUB * S) {
        const int i2 = t / S, s = t % S;
        const int vk = vk0 + i2;
        const int v  = vk / 3, k = vk % 3;
        const int p  = didx[v * 3 + k];
        s_sidx[i2][s] = spiral[p * S + s];
        if (s == 0) s_wk[i2] = dw[v * 3 + k];
    }

    // accumulators init with bias
    ull acc[8][4];
    {
        float bv[8];
        *(float4*)&bv[0] = *(const float4*)&bias[tx * 8];
        *(float4*)&bv[4] = *(const float4*)&bias[tx * 8 + 4];
#pragma unroll
        for (int ic = 0; ic < 8; ++ic) {
            const ull bp = pack2(bv[ic], bv[ic]);
#pragma unroll
            for (int ibp = 0; ibp < 4; ++ibp) acc[ic][ibp] = bp;
        }
    }
    __syncthreads();

    const size_t VinCIN = (size_t)Vin * CIN;

    for (int j0 = 0; j0 < FAN; j0 += KC) {
        // ---- stage W chunk, duplicated: Wdup[jj][2c] = (w[c], w[c]) ----
        for (int i = t; i < KC * (COUT / 2); i += 256) {
            const int jj = i / (COUT / 2);
            const int cc = i % (COUT / 2);
            const float2 w2 = *(const float2*)&W[(size_t)(j0 + jj) * COUT + cc * 2];
            *(float4*)&Ws[jj * 2 * COUT + cc * 4] = make_float4(w2.x, w2.x, w2.y, w2.y);
        }
        // ---- gather g chunk: gs[ig][jj][b], coalesced reads along j ----
        if constexpr ((256 % KC) == 0) {
            int jj = t % KC;
            int b  = (t / KC) % 32;
            int ig = t / (KC * 32);
            const int j  = j0 + jj;
            const int s  = j / CIN;
            const int ci = j % CIN;
            constexpr int BSTEP = 256 / KC;
            constexpr int E = NG / 256;
#pragma unroll
            for (int e = 0; e < E; ++e) {
                gs[ig * GSZ + jj * GSROW + b] =
                    xin[(size_t)b * VinCIN + (size_t)s_sidx[ig][s] * CIN + ci];
                b += BSTEP;
                if (b >= 32) { b -= 32; ++ig; }
            }
        } else {
            for (int i = t; i < NG; i += 256) {
                const int ig = i / (KC * 32);
                const int r  = i % (KC * 32);
                const int b  = r / KC;
                const int jj = r % KC;
                const int j  = j0 + jj;
                const int s  = j / CIN;
                const int ci = j % CIN;
                gs[ig * GSZ + jj * GSROW + b] =
                    xin[(size_t)b * VinCIN + (size_t)s_sidx[ig][s] * CIN + ci];
            }
        }
        __syncthreads();

        const ulonglong2* wq = (const ulonglong2*)Ws + tx * 4;
        const ull* gq = (const ull*)gs + inst * (GSZ / 2) + pg * 4;
#pragma unroll 4
        for (int jj = 0; jj < KC; ++jj) {
            ull wp[8];
            {
                const ulonglong2 a0 = wq[jj * (COUT / 2) + 0];
                const ulonglong2 a1 = wq[jj * (COUT / 2) + 1];
                const ulonglong2 a2 = wq[jj * (COUT / 2) + 2];
                const ulonglong2 a3 = wq[jj * (COUT / 2) + 3];
                wp[0] = a0.x; wp[1] = a0.y; wp[2] = a1.x; wp[3] = a1.y;
                wp[4] = a2.x; wp[5] = a2.y; wp[6] = a3.x; wp[7] = a3.y;
            }
            ull gp[4];
#pragma unroll
            for (int ibp = 0; ibp < 4; ++ibp) gp[ibp] = gq[jj * 17 + ibp];
#pragma unroll
            for (int ic = 0; ic < 8; ++ic)
#pragma unroll
                for (int ibp = 0; ibp < 4; ++ibp)
                    fma2(acc[ic][ibp], gp[ibp], wp[ic]);
        }
        __syncthreads();
    }

    // epilogue: ELU, * dw, store
    const float wk = s_wk[inst];
    const size_t base = (size_t)(vk0 + inst) * 32 * COUT + tx * 8;
#pragma unroll
    for (int ibp = 0; ibp < 4; ++ibp) {
        const int b0 = (pg * 4 + ibp) * 2;
        float lo[8], hi[8];
#pragma unroll
        for (int ic = 0; ic < 8; ++ic) {
            unpack2(acc[ic][ibp], lo[ic], hi[ic]);
            lo[ic] = wk * elu_f(lo[ic]);
            hi[ic] = wk * elu_f(hi[ic]);
        }
        *(float4*)&part[base + (size_t)b0 * COUT]           = make_float4(lo[0], lo[1], lo[2], lo[3]);
        *(float4*)&part[base + (size_t)b0 * COUT + 4]       = make_float4(lo[4], lo[5], lo[6], lo[7]);
        *(float4*)&part[base + (size_t)(b0 + 1) * COUT]     = make_float4(hi[0], hi[1], hi[2], hi[3]);
        *(float4*)&part[base + (size_t)(b0 + 1) * COUT + 4] = make_float4(hi[4], hi[5], hi[6], hi[7]);
    }
}

// ---------------------------------------------------------------------------
// Pool-reduce: xout[b][v][c] = sum_k part[v*3+k][b][c]
// ---------------------------------------------------------------------------
template<int COUT>
__global__ void reduce_pool(const float* __restrict__ part,
                            float* __restrict__ xout, int Vout, int total4)
{
    const int i = blockIdx.x * 256 + threadIdx.x;
    if (i >= total4) return;
    constexpr int C4 = COUT / 4;
    const int c4 = i % C4;
    const int v  = (i / C4) % Vout;
    const int b  = i / (C4 * Vout);
    const float4* p = (const float4*)part;
    float4 a0 = p[((size_t)(v * 3 + 0) * 32 + b) * C4 + c4];
    float4 a1 = p[((size_t)(v * 3 + 1) * 32 + b) * C4 + c4];
    float4 a2 = p[((size_t)(v * 3 + 2) * 32 + b) * C4 + c4];
    float4 o = make_float4(a0.x + a1.x + a2.x, a0.y + a1.y + a2.y,
                           a0.z + a1.z + a2.z, a0.w + a1.w + a2.w);
    ((float4*)xout)[((size_t)b * Vout + v) * C4 + c4] = o;
}

// ---------------------------------------------------------------------------
// FC1 partial GEMM: (32, 32768) @ (32768, 512), grid (2 ctiles x 64 ksplits)
// ---------------------------------------------------------------------------
__global__ void __launch_bounds__(256, 2) fc1_conv(
    const float* __restrict__ xf,
    const float* __restrict__ Wl1,
    float* __restrict__ partf)
{
    constexpr int KC = 64, CT = 256, LANES = 64, GSROW = 34;
    extern __shared__ float sm[];
    float* Ws = sm;                 // [KC][CT]
    float* xs = sm + KC * CT;       // [KC][GSROW]

    const int t   = threadIdx.x;
    const int tx  = t % LANES;
    const int pg  = t / LANES;
    const int ct0 = blockIdx.x * CT;
    const int k0  = blockIdx.y * 512;

    ull acc[4][4];
#pragma unroll
    for (int ic = 0; ic < 4; ++ic)
#pragma unroll
        for (int ibp = 0; ibp < 4; ++ibp) acc[ic][ibp] = 0ull;

    for (int kc = 0; kc < 512; kc += KC) {
        const int kk0 = k0 + kc;
        for (int i = t; i < KC * CT / 4; i += 256) {
            const int row = i / (CT / 4), col = i % (CT / 4);
            ((float4*)Ws)[i] = *(const float4*)&Wl1[(size_t)(kk0 + row) * 512 + ct0 + col * 4];
        }
#pragma unroll
        for (int e = 0; e < 8; ++e) {
            const int idx = e * 256 + t;
            const int b = idx / KC, jj = idx % KC;
            xs[jj * GSROW + b] = xf[(size_t)b * 32768 + kk0 + jj];
        }
        __syncthreads();

        const float* gb = xs + pg * 8;
#pragma unroll 4
        for (int jj = 0; jj < KC; ++jj) {
            const float4 w4 = *(const float4*)&Ws[jj * CT + tx * 4];
            ull wp[4];
            wp[0] = pack2(w4.x, w4.x);
            wp[1] = pack2(w4.y, w4.y);
            wp[2] = pack2(w4.z, w4.z);
            wp[3] = pack2(w4.w, w4.w);
            ull gp[4];
#pragma unroll
            for (int ibp = 0; ibp < 4; ++ibp)
                gp[ibp] = *(const ull*)&gb[jj * GSROW + 2 * ibp];
#pragma unroll
            for (int ic = 0; ic < 4; ++ic)
#pragma unroll
                for (int ibp = 0; ibp < 4; ++ibp)
                    fma2(acc[ic][ibp], gp[ibp], wp[ic]);
        }
        __syncthreads();
    }

    const size_t base = (size_t)blockIdx.y * 32 * 512 + ct0 + tx * 4;
#pragma unroll
    for (int ibp = 0; ibp < 4; ++ibp) {
        const int b0 = (pg * 4 + ibp) * 2;
        float lo[4], hi[4];
#pragma unroll
        for (int ic = 0; ic < 4; ++ic) unpack2(acc[ic][ibp], lo[ic], hi[ic]);
        *(float4*)&partf[base + (size_t)b0 * 512]       = make_float4(lo[0], lo[1], lo[2], lo[3]);
        *(float4*)&partf[base + (size_t)(b0 + 1) * 512] = make_float4(hi[0], hi[1], hi[2], hi[3]);
    }
}

__global__ void fc1_reduce(const float* __restrict__ partf,
                           const float* __restrict__ bl1,
                           float* __restrict__ h,
                           float* __restrict__ out)
{
    const int i = blockIdx.x * 256 + threadIdx.x;
    if (i < 16384) {
        float s = 0.f;
#pragma unroll
        for (int p = 0; p < 64; ++p) s += partf[p * 16384 + i];
        s += bl1[i & 511];
        s = elu_f(s);
        h[i]   = s;
        out[i] = s;
    }
}

__global__ void fc2_kernel(const float* __restrict__ h,
                           const float* __restrict__ Wl2,
                           const float* __restrict__ bl2,
                           float* __restrict__ out)
{
    const int b = blockIdx.x;
    const int c = threadIdx.x;
    float acc = bl2[c];
    for (int k = 0; k < 512; ++k)
        acc = fmaf(h[b * 512 + k], Wl2[k * 64 + c], acc);
    out[16384 + b * 64 + c] = acc;
}

// ---------------------------------------------------------------------------
// Host launcher
// ---------------------------------------------------------------------------
extern "C" void kernel_launch(void* const* d_in, const int* in_sizes, int n_in,
                              void* d_out, int out_size)
{
    int I_sp[4], I_di[4], I_dw[4], I_W[4], I_b[4];
    int I_Wl1, I_bl1, I_Wl2, I_bl2;
    if (in_sizes[2] == 8192 * 3) {           // dict order
        for (int i = 0; i < 4; ++i) {
            I_sp[i] = 1 + 5 * i; I_di[i] = 2 + 5 * i; I_dw[i] = 3 + 5 * i;
            I_W[i] = 4 + 5 * i;  I_b[i] = 5 + 5 * i;
        }
    } else {                                  // signature order
        for (int i = 0; i < 4; ++i) {
            I_sp[i] = 1 + i; I_di[i] = 5 + i; I_dw[i] = 9 + i;
            I_W[i] = 13 + 2 * i; I_b[i] = 14 + 2 * i;
        }
    }
    I_Wl1 = 21; I_bl1 = 22; I_Wl2 = 23; I_bl2 = 24;

    const float* x = (const float*)d_in[0];
    const int* sp[4]; const int* di[4]; const float* dwp[4];
    const float* W[4]; const float* b[4];
    for (int i = 0; i < 4; ++i) {
        sp[i]  = (const int*)  d_in[I_sp[i]];
        di[i]  = (const int*)  d_in[I_di[i]];
        dwp[i] = (const float*)d_in[I_dw[i]];
        W[i]   = (const float*)d_in[I_W[i]];
        b[i]   = (const float*)d_in[I_b[i]];
    }
    const float* Wl1 = (const float*)d_in[I_Wl1];
    const float* bl1 = (const float*)d_in[I_bl1];
    const float* Wl2 = (const float*)d_in[I_Wl2];
    const float* bl2 = (const float*)d_in[I_bl2];

    float *x1, *x2, *x3, *x4, *p0, *p1, *p2, *p3, *pf, *h;
    cudaGetSymbolAddress((void**)&x1, g_x1);
    cudaGetSymbolAddress((void**)&x2, g_x2);
    cudaGetSymbolAddress((void**)&x3, g_x3);
    cudaGetSymbolAddress((void**)&x4, g_x4);
    cudaGetSymbolAddress((void**)&p0, g_p0);
    cudaGetSymbolAddress((void**)&p1, g_p1);
    cudaGetSymbolAddress((void**)&p2, g_p2);
    cudaGetSymbolAddress((void**)&p3, g_p3);
    cudaGetSymbolAddress((void**)&pf, g_pf);
    cudaGetSymbolAddress((void**)&h,  g_h);
    float* out = (float*)d_out;

    // smem: (KC*2*COUT + VSUB*KC*34) * 4 bytes
    const int sm0 = (36 * 64  + 16 * 36 * 34) * 4;  //  87552
    const int sm1 = (64 * 128 + 8  * 64 * 34) * 4;  // 102400
    const int sm2 = (64 * 256 + 4  * 64 * 34) * 4;  // 100352
    const int sm3 = (32 * 512 + 2  * 32 * 34) * 4;  //  74240
    const int smf = (64 * 256 + 64 * 34) * 4;       //  74240

    cudaFuncSetAttribute(stage_conv<3,  32, 36, 16>, cudaFuncAttributeMaxDynamicSharedMemorySize, sm0);
    cudaFuncSetAttribute(stage_conv<32, 64, 64, 8 >, cudaFuncAttributeMaxDynamicSharedMemorySize, sm1);
    cudaFuncSetAttribute(stage_conv<64,128, 64, 4 >, cudaFuncAttributeMaxDynamicSharedMemorySize, sm2);
    cudaFuncSetAttribute(stage_conv<128,256,32, 2 >, cudaFuncAttributeMaxDynamicSharedMemorySize, sm3);
    cudaFuncSetAttribute(fc1_conv,                   cudaFuncAttributeMaxDynamicSharedMemorySize, smf);

    stage_conv<3,  32, 36, 16><<<1536, 256, sm0>>>(x,  sp[0], di[0], dwp[0], W[0], b[0], p0, 32768, 8192);
    reduce_pool<32><<<8192, 256>>>(p0, x1, 8192, 32 * 8192 * 8);

    stage_conv<32, 64, 64, 8 ><<<768,  256, sm1>>>(x1, sp[1], di[1], dwp[1], W[1], b[1], p1, 8192, 2048);
    reduce_pool<64><<<4096, 256>>>(p1, x2, 2048, 32 * 2048 * 16);

    stage_conv<64,128, 64, 4 ><<<384,  256, sm2>>>(x2, sp[2], di[2], dwp[2], W[2], b[2], p2, 2048, 512);
    reduce_pool<128><<<2048, 256>>>(p2, x3, 512, 32 * 512 * 32);

    stage_conv<128,256,32, 2 ><<<192,  256, sm3>>>(x3, sp[3], di[3], dwp[3], W[3], b[3], p3, 512, 128);
    reduce_pool<256><<<1024, 256>>>(p3, x4, 128, 32 * 128 * 64);

    fc1_conv<<<dim3(2, 64), 256, smf>>>(x4, Wl1, pf);
    fc1_reduce<<<64, 256>>>(pf, bl1, h, out);
    fc2_kernel<<<32, 64>>>(h, Wl2, bl2, out);
}

// round 5
// speedup vs baseline: 2.2229x; 2.2229x over previous
#include <cuda_runtime.h>
#include <cstddef>

typedef unsigned long long ull;

// ---------------------------------------------------------------------------
// Scratch (static device memory — no allocations anywhere)
// ---------------------------------------------------------------------------
__device__ float g_x1[32u * 8192u * 32u];
__device__ float g_x2[32u * 2048u * 64u];
__device__ float g_x3[32u * 512u * 128u];
__device__ float g_x4[32u * 128u * 256u];        // flat (32, 32768)
__device__ float g_p0[8192u * 3u * 32u * 32u];
__device__ float g_p1[2048u * 3u * 32u * 64u];
__device__ float g_p2[512u  * 3u * 32u * 128u];
__device__ float g_p3[128u  * 3u * 32u * 256u];
__device__ float g_pf[64u * 32u * 512u];
__device__ float g_h[32u * 512u];

// ---------------------------------------------------------------------------
// f32x2 packed helpers
// ---------------------------------------------------------------------------
__device__ __forceinline__ ull pack2(float lo, float hi) {
    ull r; asm("mov.b64 %0, {%1, %2};" : "=l"(r) : "f"(lo), "f"(hi)); return r;
}
__device__ __forceinline__ void unpack2(ull v, float& lo, float& hi) {
    asm("mov.b64 {%0, %1}, %2;" : "=f"(lo), "=f"(hi) : "l"(v));
}
__device__ __forceinline__ void fma2(ull& d, ull a, ull b) {
    asm("fma.rn.f32x2 %0, %1, %2, %0;" : "+l"(d) : "l"(a), "l"(b));
}
__device__ __forceinline__ float elu_f(float a) {
    return (a > 0.f) ? a : (__expf(a) - 1.f);
}

// ---------------------------------------------------------------------------
// Fused spiral_conv (+bias, ELU, *dw) for ONE (vertex, parent) per instance.
// Block = 256 threads = VSUB = 256/COUT instances of COUT threads.
// Instance: LANES = COUT/4 lanes (tx) x 4 pair-groups (pg).
// Thread owns 4 couts (c = tx*4+ic) x 4 batch-pairs -> 16 f32x2 accumulators.
// W staged PRE-DUPLICATED into Wsa/Wsb so each inner W load is an LDS.128 at
// 16B lane stride (conflict-free); no packing MOVs in the inner loop.
// Gather uses i = e*256 + t mapping: consecutive lanes read consecutive
// input channels of the same (batch, vertex) -> coalesced global reads.
// ---------------------------------------------------------------------------
template<int CIN, int COUT, int KC, int VSUB>
__global__ void __launch_bounds__(256, 2) stage_conv(
    const float* __restrict__ xin,     // (32, Vin, CIN)
    const int*   __restrict__ spiral,  // (Vin, 12)
    const int*   __restrict__ didx,    // (Vout, 3)
    const float* __restrict__ dw,      // (Vout, 3)
    const float* __restrict__ W,       // (12*CIN, COUT)
    const float* __restrict__ bias,    // (COUT)
    float* __restrict__ part,          // (Vout*3, 32, COUT)
    int Vin, int Vout)
{
    static_assert(VSUB * COUT == 256, "block must cover exactly VSUB instances");
    constexpr int S     = 12;
    constexpr int FAN   = S * CIN;
    constexpr int LANES = COUT / 4;
    constexpr int GSROW = 34;
    constexpr int GSZ   = KC * GSROW;          // floats per instance chunk
    constexpr int NG    = VSUB * KC * 32;      // gather elements per chunk

    extern __shared__ float sm[];
    float* Wsa = sm;                           // [KC][LANES] ulonglong2
    float* Wsb = sm + KC * COUT;               // [KC][LANES] ulonglong2
    float* gs  = sm + 2 * KC * COUT;           // [VSUB][KC][GSROW]
    __shared__ int   s_sidx[VSUB][S];
    __shared__ float s_wk[VSUB];

    const int t    = threadIdx.x;
    const int inst = t / COUT;
    const int ti   = t % COUT;
    const int tx   = ti % LANES;
    const int pg   = ti / LANES;               // 0..3
    const int vk0  = blockIdx.x * VSUB;

    if (t < VSUB * S) {
        const int i2 = t / S, s = t % S;
        const int vk = vk0 + i2;
        const int v  = vk / 3, k = vk % 3;
        const int p  = didx[v * 3 + k];
        s_sidx[i2][s] = spiral[p * S + s];
        if (s == 0) s_wk[i2] = dw[v * 3 + k];
    }

    // accumulators init with bias
    ull acc[4][4];
    {
        const float4 bv = *(const float4*)&bias[tx * 4];
#pragma unroll
        for (int ibp = 0; ibp < 4; ++ibp) {
            acc[0][ibp] = pack2(bv.x, bv.x);
            acc[1][ibp] = pack2(bv.y, bv.y);
            acc[2][ibp] = pack2(bv.z, bv.z);
            acc[3][ibp] = pack2(bv.w, bv.w);
        }
    }
    __syncthreads();

    const size_t VinCIN = (size_t)Vin * CIN;

    for (int j0 = 0; j0 < FAN; j0 += KC) {
        // ---- stage W chunk, pre-duplicated, conflict-free layout ----
        for (int i = t; i < KC * LANES; i += 256) {
            const int jj  = i / LANES;
            const int txx = i % LANES;
            const float4 w4 = *(const float4*)&W[(size_t)(j0 + jj) * COUT + txx * 4];
            ulonglong2 a, b2;
            a.x  = pack2(w4.x, w4.x); a.y  = pack2(w4.y, w4.y);
            b2.x = pack2(w4.z, w4.z); b2.y = pack2(w4.w, w4.w);
            ((ulonglong2*)Wsa)[jj * LANES + txx] = a;
            ((ulonglong2*)Wsb)[jj * LANES + txx] = b2;
        }
        // ---- gather g chunk: gs[ig][jj][b]; i = e*256 + t mapping ----
        if constexpr ((256 % KC) == 0) {
            const int jj = t % KC;
            const int j  = j0 + jj;
            const int s  = j / CIN;
            const int ci = j % CIN;
            constexpr int STEP = 256 / KC;
            int b  = t / KC;     // < 32
            int ig = 0;
#pragma unroll
            for (int e = 0; e < NG / 256; ++e) {
                gs[ig * GSZ + jj * GSROW + b] =
                    xin[(size_t)b * VinCIN + (size_t)s_sidx[ig][s] * CIN + ci];
                b += STEP;
                if (b >= 32) { b -= 32; ++ig; }
            }
        } else {
            for (int i = t; i < NG; i += 256) {
                const int ig = i / (KC * 32);
                const int r  = i % (KC * 32);
                const int b  = r / KC;
                const int jj = r % KC;
                const int j  = j0 + jj;
                const int s  = j / CIN;
                const int ci = j % CIN;
                gs[ig * GSZ + jj * GSROW + b] =
                    xin[(size_t)b * VinCIN + (size_t)s_sidx[ig][s] * CIN + ci];
            }
        }
        __syncthreads();

        const ulonglong2* wqa = (const ulonglong2*)Wsa + tx;
        const ulonglong2* wqb = (const ulonglong2*)Wsb + tx;
        const ull* gq = (const ull*)gs + inst * (GSZ / 2) + pg * 4;
#pragma unroll 4
        for (int jj = 0; jj < KC; ++jj) {
            const ulonglong2 wa = wqa[jj * LANES];
            const ulonglong2 wb = wqb[jj * LANES];
            ull gp[4];
#pragma unroll
            for (int ibp = 0; ibp < 4; ++ibp) gp[ibp] = gq[jj * 17 + ibp];
#pragma unroll
            for (int ibp = 0; ibp < 4; ++ibp) {
                fma2(acc[0][ibp], gp[ibp], wa.x);
                fma2(acc[1][ibp], gp[ibp], wa.y);
                fma2(acc[2][ibp], gp[ibp], wb.x);
                fma2(acc[3][ibp], gp[ibp], wb.y);
            }
        }
        __syncthreads();
    }

    // epilogue: ELU, * dw, store
    const float wk = s_wk[inst];
    const size_t base = (size_t)(vk0 + inst) * 32 * COUT + tx * 4;
#pragma unroll
    for (int ibp = 0; ibp < 4; ++ibp) {
        const int b0 = (pg * 4 + ibp) * 2;
        float lo[4], hi[4];
#pragma unroll
        for (int ic = 0; ic < 4; ++ic) {
            unpack2(acc[ic][ibp], lo[ic], hi[ic]);
            lo[ic] = wk * elu_f(lo[ic]);
            hi[ic] = wk * elu_f(hi[ic]);
        }
        *(float4*)&part[base + (size_t)b0 * COUT]       = make_float4(lo[0], lo[1], lo[2], lo[3]);
        *(float4*)&part[base + (size_t)(b0 + 1) * COUT] = make_float4(hi[0], hi[1], hi[2], hi[3]);
    }
}

// ---------------------------------------------------------------------------
// Pool-reduce: xout[b][v][c] = sum_k part[v*3+k][b][c]
// ---------------------------------------------------------------------------
template<int COUT>
__global__ void reduce_pool(const float* __restrict__ part,
                            float* __restrict__ xout, int Vout, int total4)
{
    const int i = blockIdx.x * 256 + threadIdx.x;
    if (i >= total4) return;
    constexpr int C4 = COUT / 4;
    const int c4 = i % C4;
    const int v  = (i / C4) % Vout;
    const int b  = i / (C4 * Vout);
    const float4* p = (const float4*)part;
    float4 a0 = p[((size_t)(v * 3 + 0) * 32 + b) * C4 + c4];
    float4 a1 = p[((size_t)(v * 3 + 1) * 32 + b) * C4 + c4];
    float4 a2 = p[((size_t)(v * 3 + 2) * 32 + b) * C4 + c4];
    float4 o = make_float4(a0.x + a1.x + a2.x, a0.y + a1.y + a2.y,
                           a0.z + a1.z + a2.z, a0.w + a1.w + a2.w);
    ((float4*)xout)[((size_t)b * Vout + v) * C4 + c4] = o;
}

// ---------------------------------------------------------------------------
// FC1 partial GEMM: (32, 32768) @ (32768, 512), grid (2 ctiles x 64 ksplits)
// ---------------------------------------------------------------------------
__global__ void __launch_bounds__(256, 2) fc1_conv(
    const float* __restrict__ xf,
    const float* __restrict__ Wl1,
    float* __restrict__ partf)
{
    constexpr int KC = 64, CT = 256, LANES = 64, GSROW = 34;
    extern __shared__ float sm[];
    float* Ws = sm;                 // [KC][CT]
    float* xs = sm + KC * CT;       // [KC][GSROW]

    const int t   = threadIdx.x;
    const int tx  = t % LANES;
    const int pg  = t / LANES;
    const int ct0 = blockIdx.x * CT;
    const int k0  = blockIdx.y * 512;

    ull acc[4][4];
#pragma unroll
    for (int ic = 0; ic < 4; ++ic)
#pragma unroll
        for (int ibp = 0; ibp < 4; ++ibp) acc[ic][ibp] = 0ull;

    for (int kc = 0; kc < 512; kc += KC) {
        const int kk0 = k0 + kc;
        for (int i = t; i < KC * CT / 4; i += 256) {
            const int row = i / (CT / 4), col = i % (CT / 4);
            ((float4*)Ws)[i] = *(const float4*)&Wl1[(size_t)(kk0 + row) * 512 + ct0 + col * 4];
        }
#pragma unroll
        for (int e = 0; e < 8; ++e) {
            const int idx = e * 256 + t;
            const int b = idx / KC, jj = idx % KC;
            xs[jj * GSROW + b] = xf[(size_t)b * 32768 + kk0 + jj];
        }
        __syncthreads();

        const float* gb = xs + pg * 8;
#pragma unroll 4
        for (int jj = 0; jj < KC; ++jj) {
            const float4 w4 = *(const float4*)&Ws[jj * CT + tx * 4];
            ull wp[4];
            wp[0] = pack2(w4.x, w4.x);
            wp[1] = pack2(w4.y, w4.y);
            wp[2] = pack2(w4.z, w4.z);
            wp[3] = pack2(w4.w, w4.w);
            ull gp[4];
#pragma unroll
            for (int ibp = 0; ibp < 4; ++ibp)
                gp[ibp] = *(const ull*)&gb[jj * GSROW + 2 * ibp];
#pragma unroll
            for (int ic = 0; ic < 4; ++ic)
#pragma unroll
                for (int ibp = 0; ibp < 4; ++ibp)
                    fma2(acc[ic][ibp], gp[ibp], wp[ic]);
        }
        __syncthreads();
    }

    const size_t base = (size_t)blockIdx.y * 32 * 512 + ct0 + tx * 4;
#pragma unroll
    for (int ibp = 0; ibp < 4; ++ibp) {
        const int b0 = (pg * 4 + ibp) * 2;
        float lo[4], hi[4];
#pragma unroll
        for (int ic = 0; ic < 4; ++ic) unpack2(acc[ic][ibp], lo[ic], hi[ic]);
        *(float4*)&partf[base + (size_t)b0 * 512]       = make_float4(lo[0], lo[1], lo[2], lo[3]);
        *(float4*)&partf[base + (size_t)(b0 + 1) * 512] = make_float4(hi[0], hi[1], hi[2], hi[3]);
    }
}

__global__ void fc1_reduce(const float* __restrict__ partf,
                           const float* __restrict__ bl1,
                           float* __restrict__ h,
                           float* __restrict__ out)
{
    const int i = blockIdx.x * 256 + threadIdx.x;
    if (i < 16384) {
        float s = 0.f;
#pragma unroll
        for (int p = 0; p < 64; ++p) s += partf[p * 16384 + i];
        s += bl1[i & 511];
        s = elu_f(s);
        h[i]   = s;
        out[i] = s;
    }
}

__global__ void fc2_kernel(const float* __restrict__ h,
                           const float* __restrict__ Wl2,
                           const float* __restrict__ bl2,
                           float* __restrict__ out)
{
    const int b = blockIdx.x;
    const int c = threadIdx.x;
    float acc = bl2[c];
    for (int k = 0; k < 512; ++k)
        acc = fmaf(h[b * 512 + k], Wl2[k * 64 + c], acc);
    out[16384 + b * 64 + c] = acc;
}

// ---------------------------------------------------------------------------
// Host launcher
// ---------------------------------------------------------------------------
extern "C" void kernel_launch(void* const* d_in, const int* in_sizes, int n_in,
                              void* d_out, int out_size)
{
    int I_sp[4], I_di[4], I_dw[4], I_W[4], I_b[4];
    int I_Wl1, I_bl1, I_Wl2, I_bl2;
    if (in_sizes[2] == 8192 * 3) {           // dict order
        for (int i = 0; i < 4; ++i) {
            I_sp[i] = 1 + 5 * i; I_di[i] = 2 + 5 * i; I_dw[i] = 3 + 5 * i;
            I_W[i] = 4 + 5 * i;  I_b[i] = 5 + 5 * i;
        }
    } else {                                  // signature order
        for (int i = 0; i < 4; ++i) {
            I_sp[i] = 1 + i; I_di[i] = 5 + i; I_dw[i] = 9 + i;
            I_W[i] = 13 + 2 * i; I_b[i] = 14 + 2 * i;
        }
    }
    I_Wl1 = 21; I_bl1 = 22; I_Wl2 = 23; I_bl2 = 24;

    const float* x = (const float*)d_in[0];
    const int* sp[4]; const int* di[4]; const float* dwp[4];
    const float* W[4]; const float* b[4];
    for (int i = 0; i < 4; ++i) {
        sp[i]  = (const int*)  d_in[I_sp[i]];
        di[i]  = (const int*)  d_in[I_di[i]];
        dwp[i] = (const float*)d_in[I_dw[i]];
        W[i]   = (const float*)d_in[I_W[i]];
        b[i]   = (const float*)d_in[I_b[i]];
    }
    const float* Wl1 = (const float*)d_in[I_Wl1];
    const float* bl1 = (const float*)d_in[I_bl1];
    const float* Wl2 = (const float*)d_in[I_Wl2];
    const float* bl2 = (const float*)d_in[I_bl2];

    float *x1, *x2, *x3, *x4, *p0, *p1, *p2, *p3, *pf, *h;
    cudaGetSymbolAddress((void**)&x1, g_x1);
    cudaGetSymbolAddress((void**)&x2, g_x2);
    cudaGetSymbolAddress((void**)&x3, g_x3);
    cudaGetSymbolAddress((void**)&x4, g_x4);
    cudaGetSymbolAddress((void**)&p0, g_p0);
    cudaGetSymbolAddress((void**)&p1, g_p1);
    cudaGetSymbolAddress((void**)&p2, g_p2);
    cudaGetSymbolAddress((void**)&p3, g_p3);
    cudaGetSymbolAddress((void**)&pf, g_pf);
    cudaGetSymbolAddress((void**)&h,  g_h);
    float* out = (float*)d_out;

    // smem: (2*KC*COUT + VSUB*KC*34) * 4 bytes
    const int sm0 = (2 * 36 * 32  + 8 * 36 * 34) * 4;  // 48384
    const int sm1 = (2 * 64 * 64  + 4 * 64 * 34) * 4;  // 67584
    const int sm2 = (2 * 64 * 128 + 2 * 64 * 34) * 4;  // 82944
    const int sm3 = (2 * 32 * 256 + 1 * 32 * 34) * 4;  // 69888
    const int smf = (64 * 256 + 64 * 34) * 4;          // 74240

    cudaFuncSetAttribute(stage_conv<3,  32, 36, 8>, cudaFuncAttributeMaxDynamicSharedMemorySize, sm0);
    cudaFuncSetAttribute(stage_conv<32, 64, 64, 4>, cudaFuncAttributeMaxDynamicSharedMemorySize, sm1);
    cudaFuncSetAttribute(stage_conv<64,128, 64, 2>, cudaFuncAttributeMaxDynamicSharedMemorySize, sm2);
    cudaFuncSetAttribute(stage_conv<128,256,32, 1>, cudaFuncAttributeMaxDynamicSharedMemorySize, sm3);
    cudaFuncSetAttribute(fc1_conv,                  cudaFuncAttributeMaxDynamicSharedMemorySize, smf);

    stage_conv<3,  32, 36, 8><<<3072, 256, sm0>>>(x,  sp[0], di[0], dwp[0], W[0], b[0], p0, 32768, 8192);
    reduce_pool<32><<<8192, 256>>>(p0, x1, 8192, 32 * 8192 * 8);

    stage_conv<32, 64, 64, 4><<<1536, 256, sm1>>>(x1, sp[1], di[1], dwp[1], W[1], b[1], p1, 8192, 2048);
    reduce_pool<64><<<4096, 256>>>(p1, x2, 2048, 32 * 2048 * 16);

    stage_conv<64,128, 64, 2><<<768,  256, sm2>>>(x2, sp[2], di[2], dwp[2], W[2], b[2], p2, 2048, 512);
    reduce_pool<128><<<2048, 256>>>(p2, x3, 512, 32 * 512 * 32);

    stage_conv<128,256,32, 1><<<384,  256, sm3>>>(x3, sp[3], di[3], dwp[3], W[3], b[3], p3, 512, 128);
    reduce_pool<256><<<1024, 256>>>(p3, x4, 128, 32 * 128 * 64);

    fc1_conv<<<dim3(2, 64), 256, smf>>>(x4, Wl1, pf);
    fc1_reduce<<<64, 256>>>(pf, bl1, h, out);
    fc2_kernel<<<32, 64>>>(h, Wl2, bl2, out);
}

// round 6
// speedup vs baseline: 2.4374x; 1.0965x over previous
#include <cuda_runtime.h>
#include <cstddef>

typedef unsigned long long ull;

// ---------------------------------------------------------------------------
// Scratch (static device memory — no allocations anywhere)
// ---------------------------------------------------------------------------
__device__ float g_x1[32u * 8192u * 32u];
__device__ float g_x2[32u * 2048u * 64u];
__device__ float g_x3[32u * 512u * 128u];
__device__ float g_x4[32u * 128u * 256u];        // flat (32, 32768)
__device__ float g_p0[8192u * 3u * 32u * 32u];
__device__ float g_p1[2048u * 3u * 32u * 64u];
__device__ float g_p2[512u  * 3u * 3u * 32u * 128u];   // KS=3 raw partials
__device__ float g_p3[128u  * 3u * 3u * 32u * 256u];   // KS=3 raw partials
__device__ float g_pf[64u * 32u * 512u];
__device__ float g_h[32u * 512u];

// ---------------------------------------------------------------------------
// f32x2 packed helpers
// ---------------------------------------------------------------------------
__device__ __forceinline__ ull pack2(float lo, float hi) {
    ull r; asm("mov.b64 %0, {%1, %2};" : "=l"(r) : "f"(lo), "f"(hi)); return r;
}
__device__ __forceinline__ void unpack2(ull v, float& lo, float& hi) {
    asm("mov.b64 {%0, %1}, %2;" : "=f"(lo), "=f"(hi) : "l"(v));
}
__device__ __forceinline__ void fma2(ull& d, ull a, ull b) {
    asm("fma.rn.f32x2 %0, %1, %2, %0;" : "+l"(d) : "l"(a), "l"(b));
}
__device__ __forceinline__ float elu_f(float a) {
    return (a > 0.f) ? a : (__expf(a) - 1.f);
}

// ---------------------------------------------------------------------------
// TC=4 fused kernel (stage0 only). Proven correct in round 5.
// ---------------------------------------------------------------------------
template<int CIN, int COUT, int KC, int VSUB>
__global__ void __launch_bounds__(256, 2) stage_conv4(
    const float* __restrict__ xin, const int* __restrict__ spiral,
    const int* __restrict__ didx, const float* __restrict__ dw,
    const float* __restrict__ W, const float* __restrict__ bias,
    float* __restrict__ part, int Vin, int Vout)
{
    static_assert(VSUB * COUT == 256, "");
    constexpr int S = 12, FAN = S * CIN, LANES = COUT / 4, GSROW = 34;
    constexpr int GSZ = KC * GSROW, NG = VSUB * KC * 32;

    extern __shared__ float sm[];
    float* Wsa = sm;
    float* Wsb = sm + KC * COUT;
    float* gs  = sm + 2 * KC * COUT;
    __shared__ int   s_sidx[VSUB][S];
    __shared__ float s_wk[VSUB];

    const int t = threadIdx.x;
    const int inst = t / COUT, ti = t % COUT;
    const int tx = ti % LANES, pg = ti / LANES;
    const int vk0 = blockIdx.x * VSUB;

    if (t < VSUB * S) {
        const int i2 = t / S, s = t % S;
        const int vk = vk0 + i2, v = vk / 3, k = vk % 3;
        const int p = didx[v * 3 + k];
        s_sidx[i2][s] = spiral[p * S + s];
        if (s == 0) s_wk[i2] = dw[v * 3 + k];
    }

    ull acc[4][4];
    {
        const float4 bv = *(const float4*)&bias[tx * 4];
#pragma unroll
        for (int ibp = 0; ibp < 4; ++ibp) {
            acc[0][ibp] = pack2(bv.x, bv.x);
            acc[1][ibp] = pack2(bv.y, bv.y);
            acc[2][ibp] = pack2(bv.z, bv.z);
            acc[3][ibp] = pack2(bv.w, bv.w);
        }
    }
    __syncthreads();

    const size_t VinCIN = (size_t)Vin * CIN;

    for (int j0 = 0; j0 < FAN; j0 += KC) {
        for (int i = t; i < KC * LANES; i += 256) {
            const int jj = i / LANES, txx = i % LANES;
            const float4 w4 = *(const float4*)&W[(size_t)(j0 + jj) * COUT + txx * 4];
            ((ulonglong2*)Wsa)[jj * LANES + txx] = make_ulonglong2(pack2(w4.x, w4.x), pack2(w4.y, w4.y));
            ((ulonglong2*)Wsb)[jj * LANES + txx] = make_ulonglong2(pack2(w4.z, w4.z), pack2(w4.w, w4.w));
        }
        for (int i = t; i < NG; i += 256) {
            const int ig = i / (KC * 32), r = i % (KC * 32);
            const int b = r / KC, jj = r % KC;
            const int j = j0 + jj, s = j / CIN, ci = j % CIN;
            gs[ig * GSZ + jj * GSROW + b] =
                xin[(size_t)b * VinCIN + (size_t)s_sidx[ig][s] * CIN + ci];
        }
        __syncthreads();

        const ulonglong2* wqa = (const ulonglong2*)Wsa + tx;
        const ulonglong2* wqb = (const ulonglong2*)Wsb + tx;
        const ull* gq = (const ull*)gs + inst * (GSZ / 2) + pg * 4;
#pragma unroll 4
        for (int jj = 0; jj < KC; ++jj) {
            const ulonglong2 wa = wqa[jj * LANES];
            const ulonglong2 wb = wqb[jj * LANES];
            ull gp[4];
#pragma unroll
            for (int ibp = 0; ibp < 4; ++ibp) gp[ibp] = gq[jj * 17 + ibp];
#pragma unroll
            for (int ibp = 0; ibp < 4; ++ibp) {
                fma2(acc[0][ibp], gp[ibp], wa.x);
                fma2(acc[1][ibp], gp[ibp], wa.y);
                fma2(acc[2][ibp], gp[ibp], wb.x);
                fma2(acc[3][ibp], gp[ibp], wb.y);
            }
        }
        __syncthreads();
    }

    const float wk = s_wk[inst];
    const size_t base = (size_t)(vk0 + inst) * 32 * COUT + tx * 4;
#pragma unroll
    for (int ibp = 0; ibp < 4; ++ibp) {
        const int b0 = (pg * 4 + ibp) * 2;
        float lo[4], hi[4];
#pragma unroll
        for (int ic = 0; ic < 4; ++ic) {
            unpack2(acc[ic][ibp], lo[ic], hi[ic]);
            lo[ic] = wk * elu_f(lo[ic]);
            hi[ic] = wk * elu_f(hi[ic]);
        }
        *(float4*)&part[base + (size_t)b0 * COUT]       = make_float4(lo[0], lo[1], lo[2], lo[3]);
        *(float4*)&part[base + (size_t)(b0 + 1) * COUT] = make_float4(hi[0], hi[1], hi[2], hi[3]);
    }
}

// ---------------------------------------------------------------------------
// TC=8 fused kernel with optional K-split (stages 1-3).
// Instance = COUT/2 threads: LANES = COUT/8 lanes (tx) x 4 pair-groups (pg).
// Thread owns 8 couts x 4 batch-pairs -> 32 f32x2 accumulators.
// Per jj: 4 LDS.128 (W, pre-duplicated, conflict-free) + 4 LDS.64 (g,
// broadcast) + 32 fma2.
// If SPLITK: grid = KS * vkBlocks (ks-major); partials stored RAW (no bias /
// ELU / dw) -> reduce_split applies bias+ELU+dw and pools.
// ---------------------------------------------------------------------------
template<int CIN, int COUT, int KC, int VSUB, int KS, bool SPLITK>
__global__ void __launch_bounds__(256, 2) stage_conv8(
    const float* __restrict__ xin, const int* __restrict__ spiral,
    const int* __restrict__ didx, const float* __restrict__ dw,
    const float* __restrict__ W, const float* __restrict__ bias,
    float* __restrict__ part,   // SPLITK: (vk, KS, 32, COUT) else (vk, 32, COUT)
    int Vin, int Vout, int vkBlocks)
{
    constexpr int S = 12, FAN = S * CIN, KPS = FAN / KS;
    constexpr int TPI = COUT / 2, LANES = COUT / 8, GSROW = 34;
    constexpr int GSZ = KC * GSROW, NG = VSUB * KC * 32;
    static_assert(VSUB * TPI == 256, "");
    static_assert(256 % KC == 0, "");
    static_assert(KPS % KC == 0, "");

    extern __shared__ float sm[];
    ulonglong2* W0 = (ulonglong2*)sm;          // 4 regions of [KC][LANES]
    ulonglong2* W1 = W0 + KC * LANES;
    ulonglong2* W2 = W1 + KC * LANES;
    ulonglong2* W3 = W2 + KC * LANES;
    float* gs = sm + 2 * KC * COUT;            // [VSUB][KC][GSROW]
    __shared__ int   s_sidx[VSUB][S];
    __shared__ float s_wk[VSUB];

    const int t = threadIdx.x;
    const int inst = t / TPI, ti = t % TPI;
    const int tx = ti % LANES, pg = ti / LANES;    // pg in 0..3
    const int bs = blockIdx.x;
    const int ksBlk = SPLITK ? (bs / vkBlocks) : 0;
    const int vk0 = (SPLITK ? (bs % vkBlocks) : bs) * VSUB;

    if (t < VSUB * S) {
        const int i2 = t / S, s = t % S;
        const int vk = vk0 + i2, v = vk / 3, k = vk % 3;
        const int p = didx[v * 3 + k];
        s_sidx[i2][s] = spiral[p * S + s];
        if (s == 0) s_wk[i2] = dw[v * 3 + k];
    }

    ull acc[8][4];
    if (SPLITK) {
#pragma unroll
        for (int ic = 0; ic < 8; ++ic)
#pragma unroll
            for (int ibp = 0; ibp < 4; ++ibp) acc[ic][ibp] = 0ull;
    } else {
        float bv[8];
        *(float4*)&bv[0] = *(const float4*)&bias[tx * 8];
        *(float4*)&bv[4] = *(const float4*)&bias[tx * 8 + 4];
#pragma unroll
        for (int ic = 0; ic < 8; ++ic) {
            const ull bp = pack2(bv[ic], bv[ic]);
#pragma unroll
            for (int ibp = 0; ibp < 4; ++ibp) acc[ic][ibp] = bp;
        }
    }
    __syncthreads();

    const size_t VinCIN = (size_t)Vin * CIN;

    for (int j0 = 0; j0 < KPS; j0 += KC) {
        const int jAbs0 = ksBlk * KPS + j0;
        // ---- stage W chunk, pre-duplicated, 4 conflict-free regions ----
        for (int i = t; i < KC * LANES; i += 256) {
            const int jj = i / LANES, txx = i % LANES;
            const float* wr = &W[(size_t)(jAbs0 + jj) * COUT + txx * 8];
            const float4 a4 = *(const float4*)wr;
            const float4 b4 = *(const float4*)(wr + 4);
            W0[jj * LANES + txx] = make_ulonglong2(pack2(a4.x, a4.x), pack2(a4.y, a4.y));
            W1[jj * LANES + txx] = make_ulonglong2(pack2(a4.z, a4.z), pack2(a4.w, a4.w));
            W2[jj * LANES + txx] = make_ulonglong2(pack2(b4.x, b4.x), pack2(b4.y, b4.y));
            W3[jj * LANES + txx] = make_ulonglong2(pack2(b4.z, b4.z), pack2(b4.w, b4.w));
        }
        // ---- gather g chunk: gs[ig][jj][b]; coalesced along channels ----
        {
            const int jj = t % KC;
            const int j  = jAbs0 + jj;
            const int s  = j / CIN;
            const int ci = j % CIN;
            constexpr int STEP = 256 / KC;
            int b = t / KC;
            int ig = 0;
#pragma unroll
            for (int e = 0; e < NG / 256; ++e) {
                gs[ig * GSZ + jj * GSROW + b] =
                    xin[(size_t)b * VinCIN + (size_t)s_sidx[ig][s] * CIN + ci];
                b += STEP;
                if (b >= 32) { b -= 32; ++ig; }
            }
        }
        __syncthreads();

        const ulonglong2* q0 = W0 + tx;
        const ulonglong2* q1 = W1 + tx;
        const ulonglong2* q2 = W2 + tx;
        const ulonglong2* q3 = W3 + tx;
        const ull* gq = (const ull*)gs + inst * (GSZ / 2) + pg * 4;
#pragma unroll 4
        for (int jj = 0; jj < KC; ++jj) {
            const ulonglong2 w0 = q0[jj * LANES];
            const ulonglong2 w1 = q1[jj * LANES];
            const ulonglong2 w2 = q2[jj * LANES];
            const ulonglong2 w3 = q3[jj * LANES];
            ull gp[4];
#pragma unroll
            for (int ibp = 0; ibp < 4; ++ibp) gp[ibp] = gq[jj * 17 + ibp];
#pragma unroll
            for (int ibp = 0; ibp < 4; ++ibp) {
                fma2(acc[0][ibp], gp[ibp], w0.x);
                fma2(acc[1][ibp], gp[ibp], w0.y);
                fma2(acc[2][ibp], gp[ibp], w1.x);
                fma2(acc[3][ibp], gp[ibp], w1.y);
                fma2(acc[4][ibp], gp[ibp], w2.x);
                fma2(acc[5][ibp], gp[ibp], w2.y);
                fma2(acc[6][ibp], gp[ibp], w3.x);
                fma2(acc[7][ibp], gp[ibp], w3.y);
            }
        }
        __syncthreads();
    }

    // epilogue
    if (SPLITK) {
        const size_t base = ((size_t)(vk0 + inst) * KS + ksBlk) * 32 * COUT + tx * 8;
#pragma unroll
        for (int ibp = 0; ibp < 4; ++ibp) {
            const int b0 = (pg * 4 + ibp) * 2;
            float lo[8], hi[8];
#pragma unroll
            for (int ic = 0; ic < 8; ++ic) unpack2(acc[ic][ibp], lo[ic], hi[ic]);
            *(float4*)&part[base + (size_t)b0 * COUT]           = make_float4(lo[0], lo[1], lo[2], lo[3]);
            *(float4*)&part[base + (size_t)b0 * COUT + 4]       = make_float4(lo[4], lo[5], lo[6], lo[7]);
            *(float4*)&part[base + (size_t)(b0 + 1) * COUT]     = make_float4(hi[0], hi[1], hi[2], hi[3]);
            *(float4*)&part[base + (size_t)(b0 + 1) * COUT + 4] = make_float4(hi[4], hi[5], hi[6], hi[7]);
        }
    } else {
        const float wk = s_wk[inst];
        const size_t base = (size_t)(vk0 + inst) * 32 * COUT + tx * 8;
#pragma unroll
        for (int ibp = 0; ibp < 4; ++ibp) {
            const int b0 = (pg * 4 + ibp) * 2;
            float lo[8], hi[8];
#pragma unroll
            for (int ic = 0; ic < 8; ++ic) {
                unpack2(acc[ic][ibp], lo[ic], hi[ic]);
                lo[ic] = wk * elu_f(lo[ic]);
                hi[ic] = wk * elu_f(hi[ic]);
            }
            *(float4*)&part[base + (size_t)b0 * COUT]           = make_float4(lo[0], lo[1], lo[2], lo[3]);
            *(float4*)&part[base + (size_t)b0 * COUT + 4]       = make_float4(lo[4], lo[5], lo[6], lo[7]);
            *(float4*)&part[base + (size_t)(b0 + 1) * COUT]     = make_float4(hi[0], hi[1], hi[2], hi[3]);
            *(float4*)&part[base + (size_t)(b0 + 1) * COUT + 4] = make_float4(hi[4], hi[5], hi[6], hi[7]);
        }
    }
}

// ---------------------------------------------------------------------------
// Pool-reduce (stage0/1): xout[b][v][c] = sum_k part[v*3+k][b][c]
// ---------------------------------------------------------------------------
template<int COUT>
__global__ void reduce_pool(const float* __restrict__ part,
                            float* __restrict__ xout, int Vout, int total4)
{
    const int i = blockIdx.x * 256 + threadIdx.x;
    if (i >= total4) return;
    constexpr int C4 = COUT / 4;
    const int c4 = i % C4;
    const int v  = (i / C4) % Vout;
    const int b  = i / (C4 * Vout);
    const float4* p = (const float4*)part;
    float4 a0 = p[((size_t)(v * 3 + 0) * 32 + b) * C4 + c4];
    float4 a1 = p[((size_t)(v * 3 + 1) * 32 + b) * C4 + c4];
    float4 a2 = p[((size_t)(v * 3 + 2) * 32 + b) * C4 + c4];
    ((float4*)xout)[((size_t)b * Vout + v) * C4 + c4] =
        make_float4(a0.x + a1.x + a2.x, a0.y + a1.y + a2.y,
                    a0.z + a1.z + a2.z, a0.w + a1.w + a2.w);
}

// ---------------------------------------------------------------------------
// K-split reduce (stage2/3): bias + ELU + dw + pool over raw partials.
// ---------------------------------------------------------------------------
template<int COUT, int KS>
__global__ void reduce_split(const float* __restrict__ part,
                             const float* __restrict__ dw,
                             const float* __restrict__ bias,
                             float* __restrict__ xout, int Vout, int total4)
{
    const int i = blockIdx.x * 256 + threadIdx.x;
    if (i >= total4) return;
    constexpr int C4 = COUT / 4;
    const int c4 = i % C4;
    const int v  = (i / C4) % Vout;
    const int b  = i / (C4 * Vout);
    const float4* p = (const float4*)part;
    const float4 bs4 = ((const float4*)bias)[c4];
    float4 o = make_float4(0.f, 0.f, 0.f, 0.f);
#pragma unroll
    for (int k = 0; k < 3; ++k) {
        float4 s = bs4;
#pragma unroll
        for (int ks = 0; ks < KS; ++ks) {
            const float4 a = p[(((size_t)(v * 3 + k) * KS + ks) * 32 + b) * C4 + c4];
            s.x += a.x; s.y += a.y; s.z += a.z; s.w += a.w;
        }
        const float wk = dw[v * 3 + k];
        o.x += wk * elu_f(s.x);
        o.y += wk * elu_f(s.y);
        o.z += wk * elu_f(s.z);
        o.w += wk * elu_f(s.w);
    }
    ((float4*)xout)[((size_t)b * Vout + v) * C4 + c4] = o;
}

// ---------------------------------------------------------------------------
// FC1 partial GEMM + reduce + FC2 (unchanged from round 5)
// ---------------------------------------------------------------------------
__global__ void __launch_bounds__(256, 2) fc1_conv(
    const float* __restrict__ xf, const float* __restrict__ Wl1,
    float* __restrict__ partf)
{
    constexpr int KC = 64, CT = 256, LANES = 64, GSROW = 34;
    extern __shared__ float sm[];
    float* Ws = sm;
    float* xs = sm + KC * CT;

    const int t = threadIdx.x;
    const int tx = t % LANES, pg = t / LANES;
    const int ct0 = blockIdx.x * CT;
    const int k0 = blockIdx.y * 512;

    ull acc[4][4];
#pragma unroll
    for (int ic = 0; ic < 4; ++ic)
#pragma unroll
        for (int ibp = 0; ibp < 4; ++ibp) acc[ic][ibp] = 0ull;

    for (int kc = 0; kc < 512; kc += KC) {
        const int kk0 = k0 + kc;
        for (int i = t; i < KC * CT / 4; i += 256) {
            const int row = i / (CT / 4), col = i % (CT / 4);
            ((float4*)Ws)[i] = *(const float4*)&Wl1[(size_t)(kk0 + row) * 512 + ct0 + col * 4];
        }
#pragma unroll
        for (int e = 0; e < 8; ++e) {
            const int idx = e * 256 + t;
            const int b = idx / KC, jj = idx % KC;
            xs[jj * GSROW + b] = xf[(size_t)b * 32768 + kk0 + jj];
        }
        __syncthreads();

        const float* gb = xs + pg * 8;
#pragma unroll 4
        for (int jj = 0; jj < KC; ++jj) {
            const float4 w4 = *(const float4*)&Ws[jj * CT + tx * 4];
            ull wp[4];
            wp[0] = pack2(w4.x, w4.x);
            wp[1] = pack2(w4.y, w4.y);
            wp[2] = pack2(w4.z, w4.z);
            wp[3] = pack2(w4.w, w4.w);
            ull gp[4];
#pragma unroll
            for (int ibp = 0; ibp < 4; ++ibp)
                gp[ibp] = *(const ull*)&gb[jj * GSROW + 2 * ibp];
#pragma unroll
            for (int ic = 0; ic < 4; ++ic)
#pragma unroll
                for (int ibp = 0; ibp < 4; ++ibp)
                    fma2(acc[ic][ibp], gp[ibp], wp[ic]);
        }
        __syncthreads();
    }

    const size_t base = (size_t)blockIdx.y * 32 * 512 + ct0 + tx * 4;
#pragma unroll
    for (int ibp = 0; ibp < 4; ++ibp) {
        const int b0 = (pg * 4 + ibp) * 2;
        float lo[4], hi[4];
#pragma unroll
        for (int ic = 0; ic < 4; ++ic) unpack2(acc[ic][ibp], lo[ic], hi[ic]);
        *(float4*)&partf[base + (size_t)b0 * 512]       = make_float4(lo[0], lo[1], lo[2], lo[3]);
        *(float4*)&partf[base + (size_t)(b0 + 1) * 512] = make_float4(hi[0], hi[1], hi[2], hi[3]);
    }
}

__global__ void fc1_reduce(const float* __restrict__ partf,
                           const float* __restrict__ bl1,
                           float* __restrict__ h, float* __restrict__ out)
{
    const int i = blockIdx.x * 256 + threadIdx.x;
    if (i < 16384) {
        float s = 0.f;
#pragma unroll
        for (int p = 0; p < 64; ++p) s += partf[p * 16384 + i];
        s += bl1[i & 511];
        s = elu_f(s);
        h[i] = s;
        out[i] = s;
    }
}

__global__ void fc2_kernel(const float* __restrict__ h,
                           const float* __restrict__ Wl2,
                           const float* __restrict__ bl2,
                           float* __restrict__ out)
{
    const int b = blockIdx.x;
    const int c = threadIdx.x;
    float acc = bl2[c];
    for (int k = 0; k < 512; ++k)
        acc = fmaf(h[b * 512 + k], Wl2[k * 64 + c], acc);
    out[16384 + b * 64 + c] = acc;
}

// ---------------------------------------------------------------------------
// Host launcher
// ---------------------------------------------------------------------------
extern "C" void kernel_launch(void* const* d_in, const int* in_sizes, int n_in,
                              void* d_out, int out_size)
{
    int I_sp[4], I_di[4], I_dw[4], I_W[4], I_b[4];
    if (in_sizes[2] == 8192 * 3) {           // dict order
        for (int i = 0; i < 4; ++i) {
            I_sp[i] = 1 + 5 * i; I_di[i] = 2 + 5 * i; I_dw[i] = 3 + 5 * i;
            I_W[i] = 4 + 5 * i;  I_b[i] = 5 + 5 * i;
        }
    } else {                                  // signature order
        for (int i = 0; i < 4; ++i) {
            I_sp[i] = 1 + i; I_di[i] = 5 + i; I_dw[i] = 9 + i;
            I_W[i] = 13 + 2 * i; I_b[i] = 14 + 2 * i;
        }
    }

    const float* x = (const float*)d_in[0];
    const int* sp[4]; const int* di[4]; const float* dwp[4];
    const float* W[4]; const float* b[4];
    for (int i = 0; i < 4; ++i) {
        sp[i]  = (const int*)  d_in[I_sp[i]];
        di[i]  = (const int*)  d_in[I_di[i]];
        dwp[i] = (const float*)d_in[I_dw[i]];
        W[i]   = (const float*)d_in[I_W[i]];
        b[i]   = (const float*)d_in[I_b[i]];
    }
    const float* Wl1 = (const float*)d_in[21];
    const float* bl1 = (const float*)d_in[22];
    const float* Wl2 = (const float*)d_in[23];
    const float* bl2 = (const float*)d_in[24];

    float *x1, *x2, *x3, *x4, *p0, *p1, *p2, *p3, *pf, *h;
    cudaGetSymbolAddress((void**)&x1, g_x1);
    cudaGetSymbolAddress((void**)&x2, g_x2);
    cudaGetSymbolAddress((void**)&x3, g_x3);
    cudaGetSymbolAddress((void**)&x4, g_x4);
    cudaGetSymbolAddress((void**)&p0, g_p0);
    cudaGetSymbolAddress((void**)&p1, g_p1);
    cudaGetSymbolAddress((void**)&p2, g_p2);
    cudaGetSymbolAddress((void**)&p3, g_p3);
    cudaGetSymbolAddress((void**)&pf, g_pf);
    cudaGetSymbolAddress((void**)&h,  g_h);
    float* out = (float*)d_out;

    // smem bytes
    const int sm0 = (2 * 36 * 32  + 8 * 36 * 34) * 4;  // 48384  (TC4 stage0)
    const int sm1 = (2 * 64 * 64  + 8 * 64 * 34) * 4;  // 102400 (TC8)
    const int sm2 = (2 * 64 * 128 + 4 * 64 * 34) * 4;  // 100352 (TC8)
    const int sm3 = (2 * 32 * 256 + 2 * 32 * 34) * 4;  // 74240  (TC8)
    const int smf = (64 * 256 + 64 * 34) * 4;          // 74240

    cudaFuncSetAttribute(stage_conv4<3, 32, 36, 8>,           cudaFuncAttributeMaxDynamicSharedMemorySize, sm0);
    cudaFuncSetAttribute(stage_conv8<32, 64, 64, 8, 1, false>, cudaFuncAttributeMaxDynamicSharedMemorySize, sm1);
    cudaFuncSetAttribute(stage_conv8<64, 128, 64, 4, 3, true>, cudaFuncAttributeMaxDynamicSharedMemorySize, sm2);
    cudaFuncSetAttribute(stage_conv8<128, 256, 32, 2, 3, true>,cudaFuncAttributeMaxDynamicSharedMemorySize, sm3);
    cudaFuncSetAttribute(fc1_conv,                             cudaFuncAttributeMaxDynamicSharedMemorySize, smf);

    // stage0: vk=24576, VSUB=8 -> 3072 blocks
    stage_conv4<3, 32, 36, 8><<<3072, 256, sm0>>>(x, sp[0], di[0], dwp[0], W[0], b[0], p0, 32768, 8192);
    reduce_pool<32><<<8192, 256>>>(p0, x1, 8192, 32 * 8192 * 8);

    // stage1: vk=6144, VSUB=8 -> 768 blocks (no K-split)
    stage_conv8<32, 64, 64, 8, 1, false><<<768, 256, sm1>>>(
        x1, sp[1], di[1], dwp[1], W[1], b[1], p1, 8192, 2048, 768);
    reduce_pool<64><<<4096, 256>>>(p1, x2, 2048, 32 * 2048 * 16);

    // stage2: vk=1536, VSUB=4, KS=3 -> vkBlocks=384, grid 1152
    stage_conv8<64, 128, 64, 4, 3, true><<<1152, 256, sm2>>>(
        x2, sp[2], di[2], dwp[2], W[2], b[2], p2, 2048, 512, 384);
    reduce_split<128, 3><<<2048, 256>>>(p2, dwp[2], b[2], x3, 512, 32 * 512 * 32);

    // stage3: vk=384, VSUB=2, KS=3 -> vkBlocks=192, grid 576
    stage_conv8<128, 256, 32, 2, 3, true><<<576, 256, sm3>>>(
        x3, sp[3], di[3], dwp[3], W[3], b[3], p3, 512, 128, 192);
    reduce_split<256, 3><<<1024, 256>>>(p3, dwp[3], b[3], x4, 128, 32 * 128 * 64);

    fc1_conv<<<dim3(2, 64), 256, smf>>>(x4, Wl1, pf);
    fc1_reduce<<<64, 256>>>(pf, bl1, h, out);
    fc2_kernel<<<32, 64>>>(h, Wl2, bl2, out);
}

// round 7
// speedup vs baseline: 2.5272x; 1.0369x over previous
#include <cuda_runtime.h>
#include <cstddef>

typedef unsigned long long ull;

// ---------------------------------------------------------------------------
// Scratch (static device memory — no allocations anywhere)
// ---------------------------------------------------------------------------
__device__ float g_xt0[32768u * 3u * 32u];       // transposed input (V,3,B)
__device__ float g_x1[32u * 8192u * 32u];
__device__ float g_x2[32u * 2048u * 64u];
__device__ float g_x3[32u * 512u * 128u];
__device__ float g_x4[32u * 128u * 256u];        // flat (32, 32768)
__device__ float g_p0[8192u * 3u * 32u * 32u];
__device__ float g_p1[2048u * 3u * 32u * 64u];
__device__ float g_p2[512u  * 3u * 3u * 32u * 128u];   // KS=3 raw partials
__device__ float g_p3[128u  * 3u * 3u * 32u * 256u];   // KS=3 raw partials
__device__ float g_pf[64u * 32u * 512u];
__device__ float g_h[32u * 512u];

// ---------------------------------------------------------------------------
// f32x2 packed helpers
// ---------------------------------------------------------------------------
__device__ __forceinline__ ull pack2(float lo, float hi) {
    ull r; asm("mov.b64 %0, {%1, %2};" : "=l"(r) : "f"(lo), "f"(hi)); return r;
}
__device__ __forceinline__ void unpack2(ull v, float& lo, float& hi) {
    asm("mov.b64 {%0, %1}, %2;" : "=f"(lo), "=f"(hi) : "l"(v));
}
__device__ __forceinline__ void fma2(ull& d, ull a, ull b) {
    asm("fma.rn.f32x2 %0, %1, %2, %0;" : "+l"(d) : "l"(a), "l"(b));
}
__device__ __forceinline__ float elu_f(float a) {
    return (a > 0.f) ? a : (__expf(a) - 1.f);
}

// ---------------------------------------------------------------------------
// Transpose x (B=32, V, 3) -> xt (V, 3, 32). Tiled via smem, conflict-free.
// ---------------------------------------------------------------------------
__global__ void __launch_bounds__(256) transpose_x(
    const float* __restrict__ x, float* __restrict__ xt)
{
    __shared__ float smt[96][33];
    const int v0 = blockIdx.x * 32;
    const int t  = threadIdx.x;
    for (int i = t; i < 32 * 96; i += 256) {
        const int b = i / 96, vc = i % 96;
        smt[vc][b] = x[(size_t)b * 98304 + v0 * 3 + vc];
    }
    __syncthreads();
    for (int i = t; i < 96 * 32; i += 256) {
        const int vc = i / 32, b = i % 32;
        xt[(size_t)(v0 * 3 + vc) * 32 + b] = smt[vc][b];
    }
}

// ---------------------------------------------------------------------------
// Stage0: TC=4 fused kernel, gather from TRANSPOSED input (V,3,32).
// Single K-chunk (FAN=36), fully coalesced 128B gather reads.
// ---------------------------------------------------------------------------
template<int COUT, int KC, int VSUB>
__global__ void __launch_bounds__(256, 2) stage_conv4t(
    const float* __restrict__ xt,      // (Vin, 3, 32)
    const int*   __restrict__ spiral,  // (Vin, 12)
    const int*   __restrict__ didx,
    const float* __restrict__ dw,
    const float* __restrict__ W,
    const float* __restrict__ bias,
    float* __restrict__ part, int Vout)
{
    static_assert(VSUB * COUT == 256, "");
    constexpr int S = 12, LANES = COUT / 4, GSROW = 34;
    constexpr int GSZ = KC * GSROW;

    extern __shared__ float sm[];
    float* Wsa = sm;
    float* Wsb = sm + KC * COUT;
    float* gs  = sm + 2 * KC * COUT;
    __shared__ int   s_sidx[VSUB][S];
    __shared__ float s_wk[VSUB];

    const int t = threadIdx.x;
    const int inst = t / COUT, ti = t % COUT;
    const int tx = ti % LANES, pg = ti / LANES;
    const int vk0 = blockIdx.x * VSUB;

    if (t < VSUB * S) {
        const int i2 = t / S, s = t % S;
        const int vk = vk0 + i2, v = vk / 3, k = vk % 3;
        const int p = didx[v * 3 + k];
        s_sidx[i2][s] = spiral[p * S + s];
        if (s == 0) s_wk[i2] = dw[v * 3 + k];
    }

    ull acc[4][4];
    {
        const float4 bv = *(const float4*)&bias[tx * 4];
#pragma unroll
        for (int ibp = 0; ibp < 4; ++ibp) {
            acc[0][ibp] = pack2(bv.x, bv.x);
            acc[1][ibp] = pack2(bv.y, bv.y);
            acc[2][ibp] = pack2(bv.z, bv.z);
            acc[3][ibp] = pack2(bv.w, bv.w);
        }
    }
    __syncthreads();

    // W staging (pre-duplicated, conflict-free)
    for (int i = t; i < KC * LANES; i += 256) {
        const int jj = i / LANES, txx = i % LANES;
        const float4 w4 = *(const float4*)&W[(size_t)jj * COUT + txx * 4];
        ((ulonglong2*)Wsa)[jj * LANES + txx] = make_ulonglong2(pack2(w4.x, w4.x), pack2(w4.y, w4.y));
        ((ulonglong2*)Wsb)[jj * LANES + txx] = make_ulonglong2(pack2(w4.z, w4.z), pack2(w4.w, w4.w));
    }
    // gather from transposed layout: 128B-contiguous per (ig,jj)
    {
        const int bb  = t & 31;
        const int row = t >> 5;
        for (int idx = row; idx < VSUB * KC; idx += 8) {
            const int ig = idx / KC, jj = idx % KC;
            const int s = jj / 3, ci = jj - s * 3;
            gs[ig * GSZ + jj * GSROW + bb] =
                xt[((size_t)s_sidx[ig][s] * 3 + ci) * 32 + bb];
        }
    }
    __syncthreads();

    const ulonglong2* wqa = (const ulonglong2*)Wsa + tx;
    const ulonglong2* wqb = (const ulonglong2*)Wsb + tx;
    const ull* gq = (const ull*)gs + inst * (GSZ / 2) + pg * 4;
#pragma unroll 4
    for (int jj = 0; jj < KC; ++jj) {
        const ulonglong2 wa = wqa[jj * LANES];
        const ulonglong2 wb = wqb[jj * LANES];
        ull gp[4];
#pragma unroll
        for (int ibp = 0; ibp < 4; ++ibp) gp[ibp] = gq[jj * 17 + ibp];
#pragma unroll
        for (int ibp = 0; ibp < 4; ++ibp) {
            fma2(acc[0][ibp], gp[ibp], wa.x);
            fma2(acc[1][ibp], gp[ibp], wa.y);
            fma2(acc[2][ibp], gp[ibp], wb.x);
            fma2(acc[3][ibp], gp[ibp], wb.y);
        }
    }
    __syncthreads();

    const float wk = s_wk[inst];
    const size_t base = (size_t)(vk0 + inst) * 32 * COUT + tx * 4;
#pragma unroll
    for (int ibp = 0; ibp < 4; ++ibp) {
        const int b0 = (pg * 4 + ibp) * 2;
        float lo[4], hi[4];
#pragma unroll
        for (int ic = 0; ic < 4; ++ic) {
            unpack2(acc[ic][ibp], lo[ic], hi[ic]);
            lo[ic] = wk * elu_f(lo[ic]);
            hi[ic] = wk * elu_f(hi[ic]);
        }
        *(float4*)&part[base + (size_t)b0 * COUT]       = make_float4(lo[0], lo[1], lo[2], lo[3]);
        *(float4*)&part[base + (size_t)(b0 + 1) * COUT] = make_float4(hi[0], hi[1], hi[2], hi[3]);
    }
}

// ---------------------------------------------------------------------------
// Stages 1-3: TC=8, double-buffered (register prefetch + ping-pong smem).
// Per chunk: LDG next chunk -> regs, compute current (hides latency), STS,
// one __syncthreads. Inner loop per jj: 4 LDS.128 (W, pre-dup, conflict-
// free) + 4 LDS.64 (g broadcast) + 32 fma2.
// ---------------------------------------------------------------------------
template<int CIN, int COUT, int KC, int VSUB, int KS, bool SPLITK>
__global__ void __launch_bounds__(256, 2) stage_conv8(
    const float* __restrict__ xin, const int* __restrict__ spiral,
    const int* __restrict__ didx, const float* __restrict__ dw,
    const float* __restrict__ W, const float* __restrict__ bias,
    float* __restrict__ part, int Vin, int Vout, int vkBlocks)
{
    constexpr int S = 12, FAN = S * CIN, KPS = FAN / KS;
    constexpr int TPI = COUT / 2, LANES = COUT / 8, GSROW = 34;
    constexpr int GSZ = KC * GSROW;
    constexpr int E_G = VSUB * KC * 32 / 256;      // gather elems / thread
    constexpr int NW  = KC * LANES;                // W items (8 floats each)
    constexpr int ITW = (NW + 255) / 256;
    constexpr int SMHALF = 2 * KC * COUT + VSUB * GSZ;  // floats per buffer
    constexpr int NCH = KPS / KC;
    static_assert(VSUB * TPI == 256, "");
    static_assert(256 % KC == 0, "");
    static_assert(KPS % KC == 0, "");

    extern __shared__ float sm[];
    __shared__ int   s_sidx[VSUB][S];
    __shared__ float s_wk[VSUB];

    const int t = threadIdx.x;
    const int inst = t / TPI, ti = t % TPI;
    const int tx = ti % LANES, pg = ti / LANES;
    const int bs = blockIdx.x;
    const int ksBlk = SPLITK ? (bs / vkBlocks) : 0;
    const int vk0 = (SPLITK ? (bs % vkBlocks) : bs) * VSUB;

    if (t < VSUB * S) {
        const int i2 = t / S, s = t % S;
        const int vk = vk0 + i2, v = vk / 3, k = vk % 3;
        const int p = didx[v * 3 + k];
        s_sidx[i2][s] = spiral[p * S + s];
        if (s == 0) s_wk[i2] = dw[v * 3 + k];
    }

    ull acc[8][4];
    if (SPLITK) {
#pragma unroll
        for (int ic = 0; ic < 8; ++ic)
#pragma unroll
            for (int ibp = 0; ibp < 4; ++ibp) acc[ic][ibp] = 0ull;
    } else {
        float bv[8];
        *(float4*)&bv[0] = *(const float4*)&bias[tx * 8];
        *(float4*)&bv[4] = *(const float4*)&bias[tx * 8 + 4];
#pragma unroll
        for (int ic = 0; ic < 8; ++ic) {
            const ull bp = pack2(bv[ic], bv[ic]);
#pragma unroll
            for (int ibp = 0; ibp < 4; ++ibp) acc[ic][ibp] = bp;
        }
    }
    __syncthreads();   // s_sidx visible before first gather

    const size_t VinCIN = (size_t)Vin * CIN;

    float4 wra[ITW], wrb[ITW];
    float  greg[E_G];

    auto load_chunk = [&](int ch) {
        const int jA0 = ksBlk * KPS + ch * KC;
#pragma unroll
        for (int w = 0; w < ITW; ++w) {
            const int i = t + 256 * w;
            if (NW >= 256 * (w + 1) || i < NW) {
                const int jj = i / LANES, txx = i % LANES;
                const float* wr = &W[(size_t)(jA0 + jj) * COUT + txx * 8];
                wra[w] = *(const float4*)wr;
                wrb[w] = *(const float4*)(wr + 4);
            }
        }
        {
            const int jj = t % KC;
            const int j  = jA0 + jj;
            const int s  = j / CIN;
            const int ci = j % CIN;
            constexpr int STEP = 256 / KC;
            int b = t / KC, ig = 0;
#pragma unroll
            for (int e = 0; e < E_G; ++e) {
                greg[e] = xin[(size_t)b * VinCIN + (size_t)s_sidx[ig][s] * CIN + ci];
                b += STEP;
                if (b >= 32) { b -= 32; ++ig; }
            }
        }
    };

    auto store_chunk = [&](int sel) {
        float* base = sm + sel * SMHALF;
        ulonglong2* W0 = (ulonglong2*)base;
        ulonglong2* W1 = W0 + KC * LANES;
        ulonglong2* W2 = W1 + KC * LANES;
        ulonglong2* W3 = W2 + KC * LANES;
        float* gsb = base + 2 * KC * COUT;
#pragma unroll
        for (int w = 0; w < ITW; ++w) {
            const int i = t + 256 * w;
            if (NW >= 256 * (w + 1) || i < NW) {
                const int jj = i / LANES, txx = i % LANES;
                W0[jj * LANES + txx] = make_ulonglong2(pack2(wra[w].x, wra[w].x), pack2(wra[w].y, wra[w].y));
                W1[jj * LANES + txx] = make_ulonglong2(pack2(wra[w].z, wra[w].z), pack2(wra[w].w, wra[w].w));
                W2[jj * LANES + txx] = make_ulonglong2(pack2(wrb[w].x, wrb[w].x), pack2(wrb[w].y, wrb[w].y));
                W3[jj * LANES + txx] = make_ulonglong2(pack2(wrb[w].z, wrb[w].z), pack2(wrb[w].w, wrb[w].w));
            }
        }
        {
            const int jj = t % KC;
            constexpr int STEP = 256 / KC;
            int b = t / KC, ig = 0;
#pragma unroll
            for (int e = 0; e < E_G; ++e) {
                gsb[ig * GSZ + jj * GSROW + b] = greg[e];
                b += STEP;
                if (b >= 32) { b -= 32; ++ig; }
            }
        }
    };

    auto compute = [&](int sel) {
        const float* base = sm + sel * SMHALF;
        const ulonglong2* q0 = (const ulonglong2*)base + tx;
        const ulonglong2* q1 = q0 + KC * LANES;
        const ulonglong2* q2 = q1 + KC * LANES;
        const ulonglong2* q3 = q2 + KC * LANES;
        const ull* gq = (const ull*)(base + 2 * KC * COUT) + inst * (GSZ / 2) + pg * 4;
#pragma unroll 4
        for (int jj = 0; jj < KC; ++jj) {
            const ulonglong2 w0 = q0[jj * LANES];
            const ulonglong2 w1 = q1[jj * LANES];
            const ulonglong2 w2 = q2[jj * LANES];
            const ulonglong2 w3 = q3[jj * LANES];
            ull gp[4];
#pragma unroll
            for (int ibp = 0; ibp < 4; ++ibp) gp[ibp] = gq[jj * 17 + ibp];
#pragma unroll
            for (int ibp = 0; ibp < 4; ++ibp) {
                fma2(acc[0][ibp], gp[ibp], w0.x);
                fma2(acc[1][ibp], gp[ibp], w0.y);
                fma2(acc[2][ibp], gp[ibp], w1.x);
                fma2(acc[3][ibp], gp[ibp], w1.y);
                fma2(acc[4][ibp], gp[ibp], w2.x);
                fma2(acc[5][ibp], gp[ibp], w2.y);
                fma2(acc[6][ibp], gp[ibp], w3.x);
                fma2(acc[7][ibp], gp[ibp], w3.y);
            }
        }
    };

    load_chunk(0);
    store_chunk(0);
    __syncthreads();
    for (int c = 0; c < NCH; ++c) {
        if (c + 1 < NCH) load_chunk(c + 1);
        compute(c & 1);
        if (c + 1 < NCH) store_chunk((c + 1) & 1);
        __syncthreads();
    }

    // epilogue
    if (SPLITK) {
        const size_t base = ((size_t)(vk0 + inst) * KS + ksBlk) * 32 * COUT + tx * 8;
#pragma unroll
        for (int ibp = 0; ibp < 4; ++ibp) {
            const int b0 = (pg * 4 + ibp) * 2;
            float lo[8], hi[8];
#pragma unroll
            for (int ic = 0; ic < 8; ++ic) unpack2(acc[ic][ibp], lo[ic], hi[ic]);
            *(float4*)&part[base + (size_t)b0 * COUT]           = make_float4(lo[0], lo[1], lo[2], lo[3]);
            *(float4*)&part[base + (size_t)b0 * COUT + 4]       = make_float4(lo[4], lo[5], lo[6], lo[7]);
            *(float4*)&part[base + (size_t)(b0 + 1) * COUT]     = make_float4(hi[0], hi[1], hi[2], hi[3]);
            *(float4*)&part[base + (size_t)(b0 + 1) * COUT + 4] = make_float4(hi[4], hi[5], hi[6], hi[7]);
        }
    } else {
        const float wk = s_wk[inst];
        const size_t base = (size_t)(vk0 + inst) * 32 * COUT + tx * 8;
#pragma unroll
        for (int ibp = 0; ibp < 4; ++ibp) {
            const int b0 = (pg * 4 + ibp) * 2;
            float lo[8], hi[8];
#pragma unroll
            for (int ic = 0; ic < 8; ++ic) {
                unpack2(acc[ic][ibp], lo[ic], hi[ic]);
                lo[ic] = wk * elu_f(lo[ic]);
                hi[ic] = wk * elu_f(hi[ic]);
            }
            *(float4*)&part[base + (size_t)b0 * COUT]           = make_float4(lo[0], lo[1], lo[2], lo[3]);
            *(float4*)&part[base + (size_t)b0 * COUT + 4]       = make_float4(lo[4], lo[5], lo[6], lo[7]);
            *(float4*)&part[base + (size_t)(b0 + 1) * COUT]     = make_float4(hi[0], hi[1], hi[2], hi[3]);
            *(float4*)&part[base + (size_t)(b0 + 1) * COUT + 4] = make_float4(hi[4], hi[5], hi[6], hi[7]);
        }
    }
}

// ---------------------------------------------------------------------------
// Pool-reduce (stage0/1): xout[b][v][c] = sum_k part[v*3+k][b][c]
// ---------------------------------------------------------------------------
template<int COUT>
__global__ void reduce_pool(const float* __restrict__ part,
                            float* __restrict__ xout, int Vout, int total4)
{
    const int i = blockIdx.x * 256 + threadIdx.x;
    if (i >= total4) return;
    constexpr int C4 = COUT / 4;
    const int c4 = i % C4;
    const int v  = (i / C4) % Vout;
    const int b  = i / (C4 * Vout);
    const float4* p = (const float4*)part;
    float4 a0 = p[((size_t)(v * 3 + 0) * 32 + b) * C4 + c4];
    float4 a1 = p[((size_t)(v * 3 + 1) * 32 + b) * C4 + c4];
    float4 a2 = p[((size_t)(v * 3 + 2) * 32 + b) * C4 + c4];
    ((float4*)xout)[((size_t)b * Vout + v) * C4 + c4] =
        make_float4(a0.x + a1.x + a2.x, a0.y + a1.y + a2.y,
                    a0.z + a1.z + a2.z, a0.w + a1.w + a2.w);
}

// ---------------------------------------------------------------------------
// K-split reduce (stage2/3): bias + ELU + dw + pool over raw partials.
// ---------------------------------------------------------------------------
template<int COUT, int KS>
__global__ void reduce_split(const float* __restrict__ part,
                             const float* __restrict__ dw,
                             const float* __restrict__ bias,
                             float* __restrict__ xout, int Vout, int total4)
{
    const int i = blockIdx.x * 256 + threadIdx.x;
    if (i >= total4) return;
    constexpr int C4 = COUT / 4;
    const int c4 = i % C4;
    const int v  = (i / C4) % Vout;
    const int b  = i / (C4 * Vout);
    const float4* p = (const float4*)part;
    const float4 bs4 = ((const float4*)bias)[c4];
    float4 o = make_float4(0.f, 0.f, 0.f, 0.f);
#pragma unroll
    for (int k = 0; k < 3; ++k) {
        float4 s = bs4;
#pragma unroll
        for (int ks = 0; ks < KS; ++ks) {
            const float4 a = p[(((size_t)(v * 3 + k) * KS + ks) * 32 + b) * C4 + c4];
            s.x += a.x; s.y += a.y; s.z += a.z; s.w += a.w;
        }
        const float wk = dw[v * 3 + k];
        o.x += wk * elu_f(s.x);
        o.y += wk * elu_f(s.y);
        o.z += wk * elu_f(s.z);
        o.w += wk * elu_f(s.w);
    }
    ((float4*)xout)[((size_t)b * Vout + v) * C4 + c4] = o;
}

// ---------------------------------------------------------------------------
// FC1 partial GEMM + reduce + FC2
// ---------------------------------------------------------------------------
__global__ void __launch_bounds__(256, 2) fc1_conv(
    const float* __restrict__ xf, const float* __restrict__ Wl1,
    float* __restrict__ partf)
{
    constexpr int KC = 64, CT = 256, LANES = 64, GSROW = 34;
    extern __shared__ float sm[];
    float* Ws = sm;
    float* xs = sm + KC * CT;

    const int t = threadIdx.x;
    const int tx = t % LANES, pg = t / LANES;
    const int ct0 = blockIdx.x * CT;
    const int k0 = blockIdx.y * 512;

    ull acc[4][4];
#pragma unroll
    for (int ic = 0; ic < 4; ++ic)
#pragma unroll
        for (int ibp = 0; ibp < 4; ++ibp) acc[ic][ibp] = 0ull;

    for (int kc = 0; kc < 512; kc += KC) {
        const int kk0 = k0 + kc;
        for (int i = t; i < KC * CT / 4; i += 256) {
            const int row = i / (CT / 4), col = i % (CT / 4);
            ((float4*)Ws)[i] = *(const float4*)&Wl1[(size_t)(kk0 + row) * 512 + ct0 + col * 4];
        }
#pragma unroll
        for (int e = 0; e < 8; ++e) {
            const int idx = e * 256 + t;
            const int b = idx / KC, jj = idx % KC;
            xs[jj * GSROW + b] = xf[(size_t)b * 32768 + kk0 + jj];
        }
        __syncthreads();

        const float* gb = xs + pg * 8;
#pragma unroll 4
        for (int jj = 0; jj < KC; ++jj) {
            const float4 w4 = *(const float4*)&Ws[jj * CT + tx * 4];
            ull wp[4];
            wp[0] = pack2(w4.x, w4.x);
            wp[1] = pack2(w4.y, w4.y);
            wp[2] = pack2(w4.z, w4.z);
            wp[3] = pack2(w4.w, w4.w);
            ull gp[4];
#pragma unroll
            for (int ibp = 0; ibp < 4; ++ibp)
                gp[ibp] = *(const ull*)&gb[jj * GSROW + 2 * ibp];
#pragma unroll
            for (int ic = 0; ic < 4; ++ic)
#pragma unroll
                for (int ibp = 0; ibp < 4; ++ibp)
                    fma2(acc[ic][ibp], gp[ibp], wp[ic]);
        }
        __syncthreads();
    }

    const size_t base = (size_t)blockIdx.y * 32 * 512 + ct0 + tx * 4;
#pragma unroll
    for (int ibp = 0; ibp < 4; ++ibp) {
        const int b0 = (pg * 4 + ibp) * 2;
        float lo[4], hi[4];
#pragma unroll
        for (int ic = 0; ic < 4; ++ic) unpack2(acc[ic][ibp], lo[ic], hi[ic]);
        *(float4*)&partf[base + (size_t)b0 * 512]       = make_float4(lo[0], lo[1], lo[2], lo[3]);
        *(float4*)&partf[base + (size_t)(b0 + 1) * 512] = make_float4(hi[0], hi[1], hi[2], hi[3]);
    }
}

__global__ void fc1_reduce(const float* __restrict__ partf,
                           const float* __restrict__ bl1,
                           float* __restrict__ h, float* __restrict__ out)
{
    const int i = blockIdx.x * 256 + threadIdx.x;
    if (i < 16384) {
        float s = 0.f;
#pragma unroll
        for (int p = 0; p < 64; ++p) s += partf[p * 16384 + i];
        s += bl1[i & 511];
        s = elu_f(s);
        h[i] = s;
        out[i] = s;
    }
}

__global__ void fc2_kernel(const float* __restrict__ h,
                           const float* __restrict__ Wl2,
                           const float* __restrict__ bl2,
                           float* __restrict__ out)
{
    const int b = blockIdx.x;
    const int c = threadIdx.x;
    float acc = bl2[c];
    for (int k = 0; k < 512; ++k)
        acc = fmaf(h[b * 512 + k], Wl2[k * 64 + c], acc);
    out[16384 + b * 64 + c] = acc;
}

// ---------------------------------------------------------------------------
// Host launcher
// ---------------------------------------------------------------------------
extern "C" void kernel_launch(void* const* d_in, const int* in_sizes, int n_in,
                              void* d_out, int out_size)
{
    int I_sp[4], I_di[4], I_dw[4], I_W[4], I_b[4];
    if (in_sizes[2] == 8192 * 3) {           // dict order
        for (int i = 0; i < 4; ++i) {
            I_sp[i] = 1 + 5 * i; I_di[i] = 2 + 5 * i; I_dw[i] = 3 + 5 * i;
            I_W[i] = 4 + 5 * i;  I_b[i] = 5 + 5 * i;
        }
    } else {                                  // signature order
        for (int i = 0; i < 4; ++i) {
            I_sp[i] = 1 + i; I_di[i] = 5 + i; I_dw[i] = 9 + i;
            I_W[i] = 13 + 2 * i; I_b[i] = 14 + 2 * i;
        }
    }

    const float* x = (const float*)d_in[0];
    const int* sp[4]; const int* di[4]; const float* dwp[4];
    const float* W[4]; const float* b[4];
    for (int i = 0; i < 4; ++i) {
        sp[i]  = (const int*)  d_in[I_sp[i]];
        di[i]  = (const int*)  d_in[I_di[i]];
        dwp[i] = (const float*)d_in[I_dw[i]];
        W[i]   = (const float*)d_in[I_W[i]];
        b[i]   = (const float*)d_in[I_b[i]];
    }
    const float* Wl1 = (const float*)d_in[21];
    const float* bl1 = (const float*)d_in[22];
    const float* Wl2 = (const float*)d_in[23];
    const float* bl2 = (const float*)d_in[24];

    float *xt0, *x1, *x2, *x3, *x4, *p0, *p1, *p2, *p3, *pf, *h;
    cudaGetSymbolAddress((void**)&xt0, g_xt0);
    cudaGetSymbolAddress((void**)&x1, g_x1);
    cudaGetSymbolAddress((void**)&x2, g_x2);
    cudaGetSymbolAddress((void**)&x3, g_x3);
    cudaGetSymbolAddress((void**)&x4, g_x4);
    cudaGetSymbolAddress((void**)&p0, g_p0);
    cudaGetSymbolAddress((void**)&p1, g_p1);
    cudaGetSymbolAddress((void**)&p2, g_p2);
    cudaGetSymbolAddress((void**)&p3, g_p3);
    cudaGetSymbolAddress((void**)&pf, g_pf);
    cudaGetSymbolAddress((void**)&h,  g_h);
    float* out = (float*)d_out;

    // smem bytes
    const int sm0 = (2 * 36 * 32 + 8 * 36 * 34) * 4;            // 48384 (stage0)
    const int sm1 = 2 * (2 * 16 * 64  + 8 * 16 * 34) * 4;       // 51200
    const int sm2 = 2 * (2 * 16 * 128 + 4 * 16 * 34) * 4;       // 50176
    const int sm3 = 2 * (2 * 16 * 256 + 2 * 16 * 34) * 4;       // 74240
    const int smf = (64 * 256 + 64 * 34) * 4;                   // 74240

    cudaFuncSetAttribute(stage_conv4t<32, 36, 8>,               cudaFuncAttributeMaxDynamicSharedMemorySize, sm0);
    cudaFuncSetAttribute(stage_conv8<32, 64, 16, 8, 1, false>,  cudaFuncAttributeMaxDynamicSharedMemorySize, sm1);
    cudaFuncSetAttribute(stage_conv8<64, 128, 16, 4, 3, true>,  cudaFuncAttributeMaxDynamicSharedMemorySize, sm2);
    cudaFuncSetAttribute(stage_conv8<128, 256, 16, 2, 3, true>, cudaFuncAttributeMaxDynamicSharedMemorySize, sm3);
    cudaFuncSetAttribute(fc1_conv,                              cudaFuncAttributeMaxDynamicSharedMemorySize, smf);

    // transpose input for stage0
    transpose_x<<<1024, 256>>>(x, xt0);

    // stage0: vk=24576, VSUB=8 -> 3072 blocks
    stage_conv4t<32, 36, 8><<<3072, 256, sm0>>>(xt0, sp[0], di[0], dwp[0], W[0], b[0], p0, 8192);
    reduce_pool<32><<<8192, 256>>>(p0, x1, 8192, 32 * 8192 * 8);

    // stage1: vk=6144, VSUB=8 -> 768 blocks (no K-split), KC=16, double-buffered
    stage_conv8<32, 64, 16, 8, 1, false><<<768, 256, sm1>>>(
        x1, sp[1], di[1], dwp[1], W[1], b[1], p1, 8192, 2048, 768);
    reduce_pool<64><<<4096, 256>>>(p1, x2, 2048, 32 * 2048 * 16);

    // stage2: vk=1536, VSUB=4, KS=3 -> vkBlocks=384, grid 1152
    stage_conv8<64, 128, 16, 4, 3, true><<<1152, 256, sm2>>>(
        x2, sp[2], di[2], dwp[2], W[2], b[2], p2, 2048, 512, 384);
    reduce_split<128, 3><<<2048, 256>>>(p2, dwp[2], b[2], x3, 512, 32 * 512 * 32);

    // stage3: vk=384, VSUB=2, KS=3 -> vkBlocks=192, grid 576
    stage_conv8<128, 256, 16, 2, 3, true><<<576, 256, sm3>>>(
        x3, sp[3], di[3], dwp[3], W[3], b[3], p3, 512, 128, 192);
    reduce_split<256, 3><<<1024, 256>>>(p3, dwp[3], b[3], x4, 128, 32 * 128 * 64);

    fc1_conv<<<dim3(2, 64), 256, smf>>>(x4, Wl1, pf);
    fc1_reduce<<<64, 256>>>(pf, bl1, h, out);
    fc2_kernel<<<32, 64>>>(h, Wl2, bl2, out);
}